// round 16
// baseline (speedup 1.0000x reference)
#include <cuda_runtime.h>
#include <cuda_fp16.h>
#include <stdint.h>

#define MAX_NODES 100000
#define MAX_EDGES 3200000
#define HID 64
#define OUTD 16
#define SLOTS 128   // bucket capacity per node (mean degree 32)

// Scratch (device globals — no allocation allowed)
__device__ __align__(16) __half g_h [MAX_NODES * HID];   // fp16 x@W1 (then *dis)
__device__ __align__(16) __half g_h2[MAX_NODES * OUTD];  // fp16 (z@W2)*dis[row]
__device__ __align__(16) __half g_z2[MAX_NODES * OUTD];  // fp16 final embeddings
__device__ float g_dis[MAX_NODES];
__device__ int   g_cnt[MAX_NODES];
__device__ int   g_bucket_src[(size_t)MAX_NODES * SLOTS]; // 51.2MB
__device__ int   g_mode;                   // 0 = int64 indices, 1 = int32

static __device__ __forceinline__ uint32_t smem_u32(const void* p) {
    return (uint32_t)__cvta_generic_to_shared(p);
}

// ---------------------------------------------------------------------------
__global__ void detect_kernel(const void* __restrict__ ei, int ne, int n) {
    __shared__ int s_any;
    int t = threadIdx.x;
    if (t == 0) s_any = 0;
    __syncthreads();
    int k = ne < 256 ? ne : 256;
    int bad = 0;
    if (t < k) {
        long long v = ((const long long*)ei)[t];
        bad = (v < 0 || v >= (long long)n) ? 1 : 0;
    }
    if (__any_sync(0xffffffffu, bad)) { if ((t & 31) == 0) s_any = 1; }
    __syncthreads();
    if (t == 0) g_mode = s_any;
}

// ---------------------------------------------------------------------------
// One-pass bucketed CSR build: slot = atomicAdd(cnt[d]); bucket[d*SLOTS+slot]=s.
// 8 edges per thread; int4 fast path in int32 mode.
__global__ void fill2_kernel(const void* __restrict__ ei, int ne, int n) {
    int base = (blockIdx.x * blockDim.x + threadIdx.x) * 8;
    if (base >= ne) return;
    if (g_mode) {
        const int* sp = (const int*)ei;
        const int* dp = sp + (size_t)ne;
        if (base + 7 < ne) {
            int4 s4a = *(const int4*)(sp + base);
            int4 s4b = *(const int4*)(sp + base + 4);
            int4 d4a = *(const int4*)(dp + base);
            int4 d4b = *(const int4*)(dp + base + 4);
            int ss[8] = { s4a.x, s4a.y, s4a.z, s4a.w, s4b.x, s4b.y, s4b.z, s4b.w };
            int dd[8] = { d4a.x, d4a.y, d4a.z, d4a.w, d4b.x, d4b.y, d4b.z, d4b.w };
            #pragma unroll
            for (int i = 0; i < 8; ++i) {
                int s = min(max(ss[i], 0), n - 1);
                int d = min(max(dd[i], 0), n - 1);
                int p = atomicAdd(&g_cnt[d], 1);
                if (p < SLOTS) g_bucket_src[(size_t)d * SLOTS + p] = s;
            }
        } else {
            for (int e = base; e < ne; ++e) {
                int s = min(max(sp[e], 0), n - 1);
                int d = min(max(dp[e], 0), n - 1);
                int p = atomicAdd(&g_cnt[d], 1);
                if (p < SLOTS) g_bucket_src[(size_t)d * SLOTS + p] = s;
            }
        }
    } else {
        const long long* sp = (const long long*)ei;
        const long long* dp = sp + (size_t)ne;
        int lim = min(base + 8, ne);
        for (int e = base; e < lim; ++e) {
            long long s = sp[e], d = dp[e];
            if (s < 0) s = 0; if (s >= n) s = n - 1;
            if (d < 0) d = 0; if (d >= n) d = n - 1;
            int p = atomicAdd(&g_cnt[(int)d], 1);
            if (p < SLOTS) g_bucket_src[(size_t)d * SLOTS + p] = (int)s;
        }
    }
}

// dis = rsqrt(deg + 1) from post-fill counters.
__global__ void dis_kernel(int n) {
    int i = blockIdx.x * blockDim.x + threadIdx.x;
    if (i < n) g_dis[i] = rsqrtf((float)g_cnt[i] + 1.0f);
}

// ---------------------------------------------------------------------------
// GEMM1 on tensor cores: 64-row CTA, 128 threads, single load phase + sync.
// g_h[r] = fp16( x[r] @ W1 )  — UNSCALED (no dependency; forks at t=0).
__global__ __launch_bounds__(128) void gemm1_kernel(
    const float* __restrict__ x, const float* __restrict__ W, int n)
{
    __shared__ __half xs[64][136];   // 64 rows x 128 k (+8 pad)
    __shared__ __half Ws[128][72];   // 128 k  x 64 n  (+8 pad)

    int t = threadIdx.x;
    int w = t >> 5, lane = t & 31;
    int row0 = blockIdx.x * 64;

    #pragma unroll
    for (int i = 0; i < 16; ++i) {
        int flat = t + i * 128;
        int r  = flat >> 5;
        int c4 = flat & 31;
        float4 v = make_float4(0.f, 0.f, 0.f, 0.f);
        if (row0 + r < n)
            v = *(const float4*)(x + (size_t)(row0 + r) * 128 + c4 * 4);
        __half2* d = (__half2*)&xs[r][c4 * 4];
        d[0] = __floats2half2_rn(v.x, v.y);
        d[1] = __floats2half2_rn(v.z, v.w);
    }
    #pragma unroll
    for (int i = 0; i < 16; ++i) {
        int flat = t + i * 128;
        int r  = flat >> 4;
        int k4 = flat & 15;
        float4 v = *(const float4*)(W + (size_t)r * 64 + k4 * 4);
        __half2* d = (__half2*)&Ws[r][k4 * 4];
        d[0] = __floats2half2_rn(v.x, v.y);
        d[1] = __floats2half2_rn(v.z, v.w);
    }
    __syncthreads();

    float c[8][4];
    #pragma unroll
    for (int j = 0; j < 8; ++j)
        #pragma unroll
        for (int q = 0; q < 4; ++q) c[j][q] = 0.f;

    #pragma unroll
    for (int kk = 0; kk < 8; ++kk) {
        uint32_t a0, a1, a2, a3;
        {
            int r = 16 * w + (lane & 15);
            int cidx = kk * 16 + (lane >> 4) * 8;
            uint32_t addr = smem_u32(&xs[r][cidx]);
            asm volatile(
                "ldmatrix.sync.aligned.m8n8.x4.shared.b16 {%0,%1,%2,%3}, [%4];"
                : "=r"(a0), "=r"(a1), "=r"(a2), "=r"(a3) : "r"(addr));
        }
        #pragma unroll
        for (int j = 0; j < 8; ++j) {
            uint32_t b0, b1;
            int rB = kk * 16 + (lane & 15);
            uint32_t addrB = smem_u32(&Ws[rB][j * 8]);
            asm volatile(
                "ldmatrix.sync.aligned.m8n8.x2.trans.shared.b16 {%0,%1}, [%2];"
                : "=r"(b0), "=r"(b1) : "r"(addrB));
            asm volatile(
                "mma.sync.aligned.m16n8k16.row.col.f32.f16.f16.f32 "
                "{%0,%1,%2,%3}, {%4,%5,%6,%7}, {%8,%9}, {%0,%1,%2,%3};"
                : "+f"(c[j][0]), "+f"(c[j][1]), "+f"(c[j][2]), "+f"(c[j][3])
                : "r"(a0), "r"(a1), "r"(a2), "r"(a3), "r"(b0), "r"(b1));
        }
    }

    int r0 = row0 + 16 * w + (lane >> 2);
    int r1 = r0 + 8;
    #pragma unroll
    for (int j = 0; j < 8; ++j) {
        int col = j * 8 + (lane & 3) * 2;
        if (r0 < n)
            *(__half2*)(g_h + (size_t)r0 * 64 + col) =
                __floats2half2_rn(c[j][0], c[j][1]);
        if (r1 < n)
            *(__half2*)(g_h + (size_t)r1 * 64 + col) =
                __floats2half2_rn(c[j][2], c[j][3]);
    }
}

// Scale ĥ rows by dis[row] in place (vectorized 8 halves / thread).
__global__ void scale_h_kernel(int n) {
    int i = blockIdx.x * blockDim.x + threadIdx.x;   // uint4 index, 8 halves
    int tot = n * 8;                                  // n * 64 / 8
    if (i >= tot) return;
    int row = i >> 3;
    float dd = g_dis[row];
    uint4 v = ((uint4*)g_h)[i];
    __half2* hp = (__half2*)&v;
    #pragma unroll
    for (int q = 0; q < 4; ++q) {
        float2 f = __half22float2(hp[q]);
        hp[q] = __floats2half2_rn(f.x * dd, f.y * dd);
    }
    ((uint4*)g_h)[i] = v;
}

// ---------------------------------------------------------------------------
// Fused gather1 + gemm2: warp per dst node; fp16 ĥ rows (128B per edge).
__global__ __launch_bounds__(256) void gather1_gemm2_kernel(
    const float* __restrict__ b1, const float* __restrict__ W2, int n)
{
    __shared__ float W2s[64 * 16];
    __shared__ float b1s[64];
    __shared__ float zs[8][64];

    int t = threadIdx.x;
    for (int i = t; i < 64 * 16; i += 256) W2s[i] = W2[i];
    if (t < 64) b1s[t] = b1[t];
    __syncthreads();

    int w = (blockIdx.x * 256 + t) >> 5;
    int wl = t >> 5;
    int lane = t & 31;
    if (w >= n) return;

    const __half2* hh = (const __half2*)g_h;
    const int* bucket = g_bucket_src + (size_t)w * SLOTS;
    int deg = min(g_cnt[w], SLOTS);
    float s0 = 0.f, s1 = 0.f;
    int j = 0;
    for (; j + 7 < deg; j += 8) {
        int idx[8];
        #pragma unroll
        for (int q = 0; q < 8; ++q) idx[q] = bucket[j + q];
        __half2 hv[8];
        #pragma unroll
        for (int q = 0; q < 8; ++q) hv[q] = hh[(size_t)idx[q] * 32 + lane];
        #pragma unroll
        for (int q = 0; q < 8; ++q) {
            float2 f = __half22float2(hv[q]);
            s0 += f.x; s1 += f.y;
        }
    }
    for (; j + 1 < deg; j += 2) {
        int ia = bucket[j], ib = bucket[j + 1];
        float2 fa = __half22float2(hh[(size_t)ia * 32 + lane]);
        float2 fb = __half22float2(hh[(size_t)ib * 32 + lane]);
        s0 += fa.x + fb.x; s1 += fa.y + fb.y;
    }
    if (j < deg) {
        int ia = bucket[j];
        float2 fa = __half22float2(hh[(size_t)ia * 32 + lane]);
        s0 += fa.x; s1 += fa.y;
    }
    float dd = g_dis[w];
    float2 hw = __half22float2(hh[(size_t)w * 32 + lane]);
    float z0 = fmaxf((s0 + hw.x) * dd + b1s[2 * lane],     0.f);
    float z1 = fmaxf((s1 + hw.y) * dd + b1s[2 * lane + 1], 0.f);
    zs[wl][2 * lane]     = z0;
    zs[wl][2 * lane + 1] = z1;
    __syncwarp();

    int c = lane & 15, hf = lane >> 4;
    float acc = 0.f;
    #pragma unroll
    for (int k = 0; k < 32; ++k) {
        int kk = 2 * k + hf;
        acc += zs[wl][kk] * W2s[kk * 16 + c];
    }
    acc += __shfl_xor_sync(0xffffffffu, acc, 16);
    float v  = acc * dd;
    float vn = __shfl_down_sync(0xffffffffu, v, 1);
    if (hf == 0 && (c & 1) == 0)
        ((__half2*)g_h2)[(size_t)w * 8 + (c >> 1)] = __floats2half2_rn(v, vn);
}

// ---------------------------------------------------------------------------
// Gather layer 2: warp per dst; 4 edge slots x 8 lanes, 2x unrolled.
__global__ void gather2_kernel(const float* __restrict__ b2, int n) {
    int w = (blockIdx.x * blockDim.x + threadIdx.x) >> 5;
    int lane = threadIdx.x & 31;
    if (w >= n) return;
    int slot = lane >> 3;
    int h    = lane & 7;
    const __half2* hh2 = (const __half2*)g_h2;
    const int* bucket = g_bucket_src + (size_t)w * SLOTS;
    int deg = min(g_cnt[w], SLOTS);
    float sx = 0.f, sy = 0.f;
    int j = slot;
    for (; j + 4 < deg; j += 8) {
        int s1 = bucket[j];
        int s2 = bucket[j + 4];
        float2 f1 = __half22float2(hh2[(size_t)s1 * 8 + h]);
        float2 f2 = __half22float2(hh2[(size_t)s2 * 8 + h]);
        sx += f1.x + f2.x; sy += f1.y + f2.y;
    }
    if (j < deg) {
        int s1 = bucket[j];
        float2 f = __half22float2(hh2[(size_t)s1 * 8 + h]);
        sx += f.x; sy += f.y;
    }
    sx += __shfl_xor_sync(0xffffffffu, sx, 8);
    sy += __shfl_xor_sync(0xffffffffu, sy, 8);
    sx += __shfl_xor_sync(0xffffffffu, sx, 16);
    sy += __shfl_xor_sync(0xffffffffu, sy, 16);
    if (slot == 0) {
        float dd = g_dis[w];
        float2 hw = __half22float2(hh2[(size_t)w * 8 + h]);
        float v0 = (sx + hw.x) * dd + b2[2 * h];
        float v1 = (sy + hw.y) * dd + b2[2 * h + 1];
        ((__half2*)g_z2)[(size_t)w * 8 + h] = __floats2half2_rn(v0, v1);
    }
}

// ---------------------------------------------------------------------------
// Decode: 2 pairs per thread (best-measured config).
static __device__ __forceinline__ float dot16_h(long long a, long long b) {
    const uint4* za = (const uint4*)(g_z2 + (size_t)a * 16);
    const uint4* zb = (const uint4*)(g_z2 + (size_t)b * 16);
    uint4 ua0 = za[0], ua1 = za[1];
    uint4 ub0 = zb[0], ub1 = zb[1];
    const __half2* ha  = (const __half2*)&ua0;
    const __half2* hb  = (const __half2*)&ub0;
    const __half2* ha1 = (const __half2*)&ua1;
    const __half2* hb1 = (const __half2*)&ub1;
    float acc = 0.f;
    #pragma unroll
    for (int q = 0; q < 4; ++q) {
        float2 u  = __half22float2(ha[q]),  v  = __half22float2(hb[q]);
        float2 u2 = __half22float2(ha1[q]), v2 = __half22float2(hb1[q]);
        acc += u.x * v.x + u.y * v.y + u2.x * v2.x + u2.y * v2.y;
    }
    return acc;
}

static __device__ __forceinline__ void get_pair(
    const void* pe, const void* ng, int i, int np, int nn, int n, int mode,
    long long& a, long long& b)
{
    if (i < np) {
        if (mode) { a = ((const int*)pe)[i]; b = ((const int*)pe)[(size_t)np + i]; }
        else      { a = ((const long long*)pe)[i]; b = ((const long long*)pe)[(size_t)np + i]; }
    } else {
        int j = i - np;
        if (mode) { a = ((const int*)ng)[j]; b = ((const int*)ng)[(size_t)nn + j]; }
        else      { a = ((const long long*)ng)[j]; b = ((const long long*)ng)[(size_t)nn + j]; }
    }
    if (a < 0) a = 0; if (a >= n) a = n - 1;
    if (b < 0) b = 0; if (b >= n) b = n - 1;
}

__global__ void decode_kernel(const void* __restrict__ pe,
                              const void* __restrict__ ng,
                              float* __restrict__ out, int np, int nn, int n) {
    int i0 = (blockIdx.x * blockDim.x + threadIdx.x) * 2;
    int tot = np + nn;
    if (i0 >= tot) return;
    int mode = g_mode;
    long long a0, b0, a1 = 0, b1 = 0;
    get_pair(pe, ng, i0, np, nn, n, mode, a0, b0);
    bool two = (i0 + 1 < tot);
    if (two) get_pair(pe, ng, i0 + 1, np, nn, n, mode, a1, b1);
    float r0 = dot16_h(a0, b0);
    float r1 = two ? dot16_h(a1, b1) : 0.f;
    out[i0] = r0;
    if (two) out[i0 + 1] = r1;
}

// ---------------------------------------------------------------------------
extern "C" void kernel_launch(void* const* d_in, const int* in_sizes, int n_in,
                              void* d_out, int out_size) {
    const float* x   = (const float*)d_in[0];
    const void*  ei  = d_in[1];
    const void*  pe  = d_in[2];
    const void*  ng  = d_in[3];
    const float* W1  = (const float*)d_in[4];
    const float* b1  = (const float*)d_in[5];
    const float* W2  = (const float*)d_in[6];
    const float* b2  = (const float*)d_in[7];
    float*       out = (float*)d_out;

    int n  = in_sizes[0] / 128;
    int ne = in_sizes[1] / 2;
    int np = in_sizes[2] / 2;
    int nn = in_sizes[3] / 2;
    int ne8 = (ne + 7) / 8;
    int tot2 = (np + nn + 1) / 2;

    static bool s_init = false;
    static cudaStream_t s_str1;
    static cudaEvent_t s_ev_fork, s_ev_join;
    if (!s_init) {
        cudaStreamCreateWithFlags(&s_str1, cudaStreamNonBlocking);
        cudaEventCreateWithFlags(&s_ev_fork, cudaEventDisableTiming);
        cudaEventCreateWithFlags(&s_ev_join, cudaEventDisableTiming);
        s_init = true;
    }

    // Fork gemm1 at t=0 — depends only on x and W1 (unscaled output).
    cudaEventRecord(s_ev_fork, 0);
    cudaStreamWaitEvent(s_str1, s_ev_fork, 0);
    gemm1_kernel<<<(n + 63) / 64, 128, 0, s_str1>>>(x, W1, n);
    cudaEventRecord(s_ev_join, s_str1);

    // Bucketed CSR build on the main stream (no count/scan passes).
    void* cnt_ptr = nullptr;
    cudaGetSymbolAddress(&cnt_ptr, g_cnt);
    cudaMemsetAsync(cnt_ptr, 0, (size_t)n * sizeof(int));

    detect_kernel<<<1, 256>>>(ei, ne, n);
    fill2_kernel<<<(ne8 + 255) / 256, 256>>>(ei, ne, n);
    dis_kernel<<<(n + 255) / 256, 256>>>(n);

    // Join gemm1, then scale ĥ by dis[row] (restores pre-scaled form).
    cudaStreamWaitEvent(0, s_ev_join, 0);
    scale_h_kernel<<<(n * 8 + 255) / 256, 256>>>(n);

    gather1_gemm2_kernel<<<(n + 7) / 8, 256>>>(b1, W2, n);
    gather2_kernel<<<(n + 7) / 8, 256>>>(b2, n);
    decode_kernel<<<(tot2 + 255) / 256, 256>>>(pe, ng, out, np, nn, n);
}

// round 17
// speedup vs baseline: 1.0825x; 1.0825x over previous
#include <cuda_runtime.h>
#include <cuda_fp16.h>
#include <stdint.h>

#define MAX_NODES 100000
#define MAX_EDGES 3200000
#define HID 64
#define OUTD 16

// Scratch (device globals — no allocation allowed)
__device__ __align__(16) __half g_h [MAX_NODES * HID];   // fp16 (x@W1)*dis[row]
__device__ __align__(16) __half g_h2[MAX_NODES * OUTD];  // fp16 (z@W2)*dis[row]
__device__ __align__(16) __half g_z2[MAX_NODES * OUTD];  // fp16 final embeddings
__device__ float g_dis[MAX_NODES];
__device__ int   g_counts[MAX_NODES];
__device__ int   g_off[MAX_NODES + 1];
__device__ int   g_cursor[MAX_NODES];
__device__ int   g_csr_src[MAX_EDGES];
__device__ int   g_blocksums[128];
__device__ unsigned long long g_sink;

static __device__ __forceinline__ uint32_t smem_u32(const void* p) {
    return (uint32_t)__cvta_generic_to_shared(p);
}

// Inline per-block dtype detection: sample 32 int64-interpretations of the
// given index buffer; all in [0,n) => int64 (mode 0), else int32 (mode 1).
// For random int32 indices, P(false int64) = (1e-5)^32 ~ 0.
static __device__ __forceinline__ int detect_mode_block(
    const void* buf, int cnt64, int n, int* s_mode)
{
    int t = threadIdx.x;
    if (t < 32) {
        int k = cnt64 < 32 ? cnt64 : 32;
        int bad = 0;
        if (t < k) {
            long long v = ((const long long*)buf)[t];
            bad = (v < 0 || v >= (long long)n) ? 1 : 0;
        }
        unsigned m = __ballot_sync(0xffffffffu, bad);
        if (t == 0) *s_mode = (m != 0) ? 1 : 0;
    }
    __syncthreads();
    return *s_mode;
}

// ---------------------------------------------------------------------------
// Histogram of dst. 8 edges per thread; int4 fast path in int32 mode.
__global__ void count_kernel(const void* __restrict__ ei, int ne, int n) {
    __shared__ int s_mode;
    int mode = detect_mode_block(ei, ne, n, &s_mode);
    int base = (blockIdx.x * blockDim.x + threadIdx.x) * 8;
    if (base >= ne) return;
    if (mode) {
        const int* dp = (const int*)ei + (size_t)ne;
        if (base + 7 < ne) {
            int4 d4a = *(const int4*)(dp + base);
            int4 d4b = *(const int4*)(dp + base + 4);
            int d[8] = { d4a.x, d4a.y, d4a.z, d4a.w, d4b.x, d4b.y, d4b.z, d4b.w };
            #pragma unroll
            for (int i = 0; i < 8; ++i)
                atomicAdd(&g_counts[min(max(d[i], 0), n - 1)], 1);
        } else {
            for (int e = base; e < ne; ++e)
                atomicAdd(&g_counts[min(max(dp[e], 0), n - 1)], 1);
        }
    } else {
        const long long* dp = (const long long*)ei + (size_t)ne;
        int lim = min(base + 8, ne);
        for (int e = base; e < lim; ++e) {
            long long d = dp[e];
            if (d < 0) d = 0; if (d >= n) d = n - 1;
            atomicAdd(&g_counts[(int)d], 1);
        }
    }
}

// ---------------------------------------------------------------------------
// Phase 1 of scan: per-1024-block sums; also emits dis = rsqrt(deg+1).
__global__ void reduce_kernel(int n) {
    int t = threadIdx.x;
    int base = blockIdx.x * 1024 + t * 4;
    int s = 0;
    #pragma unroll
    for (int i = 0; i < 4; ++i) {
        int idx = base + i;
        if (idx < n) {
            int c = g_counts[idx];
            s += c;
            g_dis[idx] = rsqrtf((float)c + 1.0f);
        }
    }
    #pragma unroll
    for (int o = 16; o; o >>= 1) s += __shfl_down_sync(0xffffffffu, s, o);
    __shared__ int ws[8];
    if ((t & 31) == 0) ws[t >> 5] = s;
    __syncthreads();
    if (t == 0) {
        int tot = 0;
        #pragma unroll
        for (int i = 0; i < 8; ++i) tot += ws[i];
        g_blocksums[blockIdx.x] = tot;
    }
}

// ---------------------------------------------------------------------------
// GEMM1 on tensor cores: 64-row CTA, 128 threads, single load phase + sync.
// g_h[r] = fp16( (x[r] @ W1) * dis[r] ).
__global__ __launch_bounds__(128) void gemm1_kernel(
    const float* __restrict__ x, const float* __restrict__ W, int n)
{
    __shared__ __half xs[64][136];   // 64 rows x 128 k (+8 pad)
    __shared__ __half Ws[128][72];   // 128 k  x 64 n  (+8 pad)

    int t = threadIdx.x;
    int w = t >> 5, lane = t & 31;
    int row0 = blockIdx.x * 64;

    #pragma unroll
    for (int i = 0; i < 16; ++i) {
        int flat = t + i * 128;
        int r  = flat >> 5;
        int c4 = flat & 31;
        float4 v = make_float4(0.f, 0.f, 0.f, 0.f);
        if (row0 + r < n)
            v = *(const float4*)(x + (size_t)(row0 + r) * 128 + c4 * 4);
        __half2* d = (__half2*)&xs[r][c4 * 4];
        d[0] = __floats2half2_rn(v.x, v.y);
        d[1] = __floats2half2_rn(v.z, v.w);
    }
    #pragma unroll
    for (int i = 0; i < 16; ++i) {
        int flat = t + i * 128;
        int r  = flat >> 4;
        int k4 = flat & 15;
        float4 v = *(const float4*)(W + (size_t)r * 64 + k4 * 4);
        __half2* d = (__half2*)&Ws[r][k4 * 4];
        d[0] = __floats2half2_rn(v.x, v.y);
        d[1] = __floats2half2_rn(v.z, v.w);
    }
    __syncthreads();

    float c[8][4];
    #pragma unroll
    for (int j = 0; j < 8; ++j)
        #pragma unroll
        for (int q = 0; q < 4; ++q) c[j][q] = 0.f;

    #pragma unroll
    for (int kk = 0; kk < 8; ++kk) {
        uint32_t a0, a1, a2, a3;
        {
            int r = 16 * w + (lane & 15);
            int cidx = kk * 16 + (lane >> 4) * 8;
            uint32_t addr = smem_u32(&xs[r][cidx]);
            asm volatile(
                "ldmatrix.sync.aligned.m8n8.x4.shared.b16 {%0,%1,%2,%3}, [%4];"
                : "=r"(a0), "=r"(a1), "=r"(a2), "=r"(a3) : "r"(addr));
        }
        #pragma unroll
        for (int j = 0; j < 8; ++j) {
            uint32_t b0, b1;
            int rB = kk * 16 + (lane & 15);
            uint32_t addrB = smem_u32(&Ws[rB][j * 8]);
            asm volatile(
                "ldmatrix.sync.aligned.m8n8.x2.trans.shared.b16 {%0,%1}, [%2];"
                : "=r"(b0), "=r"(b1) : "r"(addrB));
            asm volatile(
                "mma.sync.aligned.m16n8k16.row.col.f32.f16.f16.f32 "
                "{%0,%1,%2,%3}, {%4,%5,%6,%7}, {%8,%9}, {%0,%1,%2,%3};"
                : "+f"(c[j][0]), "+f"(c[j][1]), "+f"(c[j][2]), "+f"(c[j][3])
                : "r"(a0), "r"(a1), "r"(a2), "r"(a3), "r"(b0), "r"(b1));
        }
    }

    int r0 = row0 + 16 * w + (lane >> 2);
    int r1 = r0 + 8;
    float d0 = (r0 < n) ? g_dis[r0] : 0.f;
    float d1 = (r1 < n) ? g_dis[r1] : 0.f;
    #pragma unroll
    for (int j = 0; j < 8; ++j) {
        int col = j * 8 + (lane & 3) * 2;
        if (r0 < n)
            *(__half2*)(g_h + (size_t)r0 * 64 + col) =
                __floats2half2_rn(c[j][0] * d0, c[j][1] * d0);
        if (r1 < n)
            *(__half2*)(g_h + (size_t)r1 * 64 + col) =
                __floats2half2_rn(c[j][2] * d1, c[j][3] * d1);
    }
}

// ---------------------------------------------------------------------------
// Scan apply with inline block-sum scan.
__global__ void scan_apply_kernel(int n, int nb) {
    __shared__ int bs[130];
    int t = threadIdx.x;
    if (t < nb) bs[t] = g_blocksums[t];
    __syncthreads();
    if (t == 0) {
        int r = 0;
        for (int i = 0; i < nb; ++i) { int a = bs[i]; bs[i] = r; r += a; }
        if (blockIdx.x == 0) g_off[n] = r;
    }
    __syncthreads();
    int blockoff = bs[blockIdx.x];

    int base = blockIdx.x * 1024 + t * 4;
    int v[4]; int s = 0;
    #pragma unroll
    for (int i = 0; i < 4; ++i) {
        v[i] = (base + i < n) ? g_counts[base + i] : 0;
        s += v[i];
    }
    int x = s;
    #pragma unroll
    for (int o = 1; o < 32; o <<= 1) {
        int u = __shfl_up_sync(0xffffffffu, x, o);
        if ((t & 31) >= o) x += u;
    }
    __shared__ int ws[8], wo[8];
    if ((t & 31) == 31) ws[t >> 5] = x;
    __syncthreads();
    if (t == 0) {
        int r = 0;
        #pragma unroll
        for (int i = 0; i < 8; ++i) { int a = ws[i]; wo[i] = r; r += a; }
    }
    __syncthreads();
    int run = x - s + wo[t >> 5] + blockoff;
    #pragma unroll
    for (int i = 0; i < 4; ++i) {
        int idx = base + i;
        if (idx < n) {
            g_off[idx] = run;
            g_cursor[idx] = run;
            run += v[i];
        }
    }
}

// CSR fill: 8 edges per thread; int4 fast path in int32 mode.
__global__ void fill_kernel(const void* __restrict__ ei, int ne, int n) {
    __shared__ int s_mode;
    int mode = detect_mode_block(ei, ne, n, &s_mode);
    int base = (blockIdx.x * blockDim.x + threadIdx.x) * 8;
    if (base >= ne) return;
    if (mode) {
        const int* sp = (const int*)ei;
        const int* dp = sp + (size_t)ne;
        if (base + 7 < ne) {
            int4 s4a = *(const int4*)(sp + base);
            int4 s4b = *(const int4*)(sp + base + 4);
            int4 d4a = *(const int4*)(dp + base);
            int4 d4b = *(const int4*)(dp + base + 4);
            int ss[8] = { s4a.x, s4a.y, s4a.z, s4a.w, s4b.x, s4b.y, s4b.z, s4b.w };
            int dd[8] = { d4a.x, d4a.y, d4a.z, d4a.w, d4b.x, d4b.y, d4b.z, d4b.w };
            #pragma unroll
            for (int i = 0; i < 8; ++i) {
                int s = min(max(ss[i], 0), n - 1);
                int d = min(max(dd[i], 0), n - 1);
                int p = atomicAdd(&g_cursor[d], 1);
                if (p >= 0 && p < ne) g_csr_src[p] = s;
            }
        } else {
            for (int e = base; e < ne; ++e) {
                int s = min(max(sp[e], 0), n - 1);
                int d = min(max(dp[e], 0), n - 1);
                int p = atomicAdd(&g_cursor[d], 1);
                if (p >= 0 && p < ne) g_csr_src[p] = s;
            }
        }
    } else {
        const long long* sp = (const long long*)ei;
        const long long* dp = sp + (size_t)ne;
        int lim = min(base + 8, ne);
        for (int e = base; e < lim; ++e) {
            long long s = sp[e], d = dp[e];
            if (s < 0) s = 0; if (s >= n) s = n - 1;
            if (d < 0) d = 0; if (d >= n) d = n - 1;
            int p = atomicAdd(&g_cursor[(int)d], 1);
            if (p >= 0 && p < ne) g_csr_src[p] = (int)s;
        }
    }
}

// ---------------------------------------------------------------------------
// L2 prefetch of the decode index arrays (runs on the side stream, DRAM-idle
// window during the gathers). Loads are kept alive via a data-dependent
// (never-true in practice, but deterministic) sink store.
__global__ void prefetch_kernel(const int* __restrict__ p1, int w1,
                                const int* __restrict__ p2, int w2) {
    int i = blockIdx.x * blockDim.x + threadIdx.x;
    int stride = gridDim.x * blockDim.x;
    unsigned s = 0;
    for (int j = i; j < (w1 >> 2); j += stride) {
        uint4 v = ((const uint4*)p1)[j];
        s += v.x + v.y + v.z + v.w;
    }
    for (int j = i; j < (w2 >> 2); j += stride) {
        uint4 v = ((const uint4*)p2)[j];
        s += v.x + v.y + v.z + v.w;
    }
    if (s == 0xDEADBEEFu && i == 0) g_sink = s;
}

// ---------------------------------------------------------------------------
// Fused gather1 + gemm2: warp per dst node; fp16 ĥ rows (128B per edge).
__global__ __launch_bounds__(256) void gather1_gemm2_kernel(
    const float* __restrict__ b1, const float* __restrict__ W2, int n)
{
    __shared__ float W2s[64 * 16];
    __shared__ float b1s[64];
    __shared__ float zs[8][64];

    int t = threadIdx.x;
    for (int i = t; i < 64 * 16; i += 256) W2s[i] = W2[i];
    if (t < 64) b1s[t] = b1[t];
    __syncthreads();

    int w = (blockIdx.x * 256 + t) >> 5;
    int wl = t >> 5;
    int lane = t & 31;
    if (w >= n) return;

    const __half2* hh = (const __half2*)g_h;
    int beg = g_off[w], end = g_off[w + 1];
    float s0 = 0.f, s1 = 0.f;
    int j = beg;
    for (; j + 7 < end; j += 8) {
        int idx[8];
        #pragma unroll
        for (int q = 0; q < 8; ++q) idx[q] = g_csr_src[j + q];
        __half2 hv[8];
        #pragma unroll
        for (int q = 0; q < 8; ++q) hv[q] = hh[(size_t)idx[q] * 32 + lane];
        #pragma unroll
        for (int q = 0; q < 8; ++q) {
            float2 f = __half22float2(hv[q]);
            s0 += f.x; s1 += f.y;
        }
    }
    for (; j + 1 < end; j += 2) {
        int ia = g_csr_src[j], ib = g_csr_src[j + 1];
        float2 fa = __half22float2(hh[(size_t)ia * 32 + lane]);
        float2 fb = __half22float2(hh[(size_t)ib * 32 + lane]);
        s0 += fa.x + fb.x; s1 += fa.y + fb.y;
    }
    if (j < end) {
        int ia = g_csr_src[j];
        float2 fa = __half22float2(hh[(size_t)ia * 32 + lane]);
        s0 += fa.x; s1 += fa.y;
    }
    float dd = g_dis[w];
    float2 hw = __half22float2(hh[(size_t)w * 32 + lane]);
    float z0 = fmaxf((s0 + hw.x) * dd + b1s[2 * lane],     0.f);
    float z1 = fmaxf((s1 + hw.y) * dd + b1s[2 * lane + 1], 0.f);
    zs[wl][2 * lane]     = z0;
    zs[wl][2 * lane + 1] = z1;
    __syncwarp();

    int c = lane & 15, hf = lane >> 4;
    float acc = 0.f;
    #pragma unroll
    for (int k = 0; k < 32; ++k) {
        int kk = 2 * k + hf;
        acc += zs[wl][kk] * W2s[kk * 16 + c];
    }
    acc += __shfl_xor_sync(0xffffffffu, acc, 16);
    float v  = acc * dd;
    float vn = __shfl_down_sync(0xffffffffu, v, 1);
    if (hf == 0 && (c & 1) == 0)
        ((__half2*)g_h2)[(size_t)w * 8 + (c >> 1)] = __floats2half2_rn(v, vn);
}

// ---------------------------------------------------------------------------
// Gather layer 2: warp per dst; 4 edge slots x 8 lanes, 2x unrolled.
__global__ void gather2_kernel(const float* __restrict__ b2, int n) {
    int w = (blockIdx.x * blockDim.x + threadIdx.x) >> 5;
    int lane = threadIdx.x & 31;
    if (w >= n) return;
    int slot = lane >> 3;
    int h    = lane & 7;
    const __half2* hh2 = (const __half2*)g_h2;
    int beg = g_off[w], end = g_off[w + 1];
    float sx = 0.f, sy = 0.f;
    int j = beg + slot;
    for (; j + 4 < end; j += 8) {
        int s1 = g_csr_src[j];
        int s2 = g_csr_src[j + 4];
        float2 f1 = __half22float2(hh2[(size_t)s1 * 8 + h]);
        float2 f2 = __half22float2(hh2[(size_t)s2 * 8 + h]);
        sx += f1.x + f2.x; sy += f1.y + f2.y;
    }
    if (j < end) {
        int s1 = g_csr_src[j];
        float2 f = __half22float2(hh2[(size_t)s1 * 8 + h]);
        sx += f.x; sy += f.y;
    }
    sx += __shfl_xor_sync(0xffffffffu, sx, 8);
    sy += __shfl_xor_sync(0xffffffffu, sy, 8);
    sx += __shfl_xor_sync(0xffffffffu, sx, 16);
    sy += __shfl_xor_sync(0xffffffffu, sy, 16);
    if (slot == 0) {
        float dd = g_dis[w];
        float2 hw = __half22float2(hh2[(size_t)w * 8 + h]);
        float v0 = (sx + hw.x) * dd + b2[2 * h];
        float v1 = (sy + hw.y) * dd + b2[2 * h + 1];
        ((__half2*)g_z2)[(size_t)w * 8 + h] = __floats2half2_rn(v0, v1);
    }
}

// ---------------------------------------------------------------------------
// Decode: 2 pairs per thread (best-measured config); inline mode detection.
static __device__ __forceinline__ float dot16_h(long long a, long long b) {
    const uint4* za = (const uint4*)(g_z2 + (size_t)a * 16);
    const uint4* zb = (const uint4*)(g_z2 + (size_t)b * 16);
    uint4 ua0 = za[0], ua1 = za[1];
    uint4 ub0 = zb[0], ub1 = zb[1];
    const __half2* ha  = (const __half2*)&ua0;
    const __half2* hb  = (const __half2*)&ub0;
    const __half2* ha1 = (const __half2*)&ua1;
    const __half2* hb1 = (const __half2*)&ub1;
    float acc = 0.f;
    #pragma unroll
    for (int q = 0; q < 4; ++q) {
        float2 u  = __half22float2(ha[q]),  v  = __half22float2(hb[q]);
        float2 u2 = __half22float2(ha1[q]), v2 = __half22float2(hb1[q]);
        acc += u.x * v.x + u.y * v.y + u2.x * v2.x + u2.y * v2.y;
    }
    return acc;
}

static __device__ __forceinline__ void get_pair(
    const void* pe, const void* ng, int i, int np, int nn, int n, int mode,
    long long& a, long long& b)
{
    if (i < np) {
        if (mode) { a = ((const int*)pe)[i]; b = ((const int*)pe)[(size_t)np + i]; }
        else      { a = ((const long long*)pe)[i]; b = ((const long long*)pe)[(size_t)np + i]; }
    } else {
        int j = i - np;
        if (mode) { a = ((const int*)ng)[j]; b = ((const int*)ng)[(size_t)nn + j]; }
        else      { a = ((const long long*)ng)[j]; b = ((const long long*)ng)[(size_t)nn + j]; }
    }
    if (a < 0) a = 0; if (a >= n) a = n - 1;
    if (b < 0) b = 0; if (b >= n) b = n - 1;
}

__global__ void decode_kernel(const void* __restrict__ pe,
                              const void* __restrict__ ng,
                              float* __restrict__ out, int np, int nn, int n) {
    __shared__ int s_mode;
    int mode = detect_mode_block(pe, np, n, &s_mode);
    int i0 = (blockIdx.x * blockDim.x + threadIdx.x) * 2;
    int tot = np + nn;
    if (i0 >= tot) return;
    long long a0, b0, a1 = 0, b1 = 0;
    get_pair(pe, ng, i0, np, nn, n, mode, a0, b0);
    bool two = (i0 + 1 < tot);
    if (two) get_pair(pe, ng, i0 + 1, np, nn, n, mode, a1, b1);
    float r0 = dot16_h(a0, b0);
    float r1 = two ? dot16_h(a1, b1) : 0.f;
    out[i0] = r0;
    if (two) out[i0 + 1] = r1;
}

// ---------------------------------------------------------------------------
extern "C" void kernel_launch(void* const* d_in, const int* in_sizes, int n_in,
                              void* d_out, int out_size) {
    const float* x   = (const float*)d_in[0];
    const void*  ei  = d_in[1];
    const void*  pe  = d_in[2];
    const void*  ng  = d_in[3];
    const float* W1  = (const float*)d_in[4];
    const float* b1  = (const float*)d_in[5];
    const float* W2  = (const float*)d_in[6];
    const float* b2  = (const float*)d_in[7];
    float*       out = (float*)d_out;

    int n  = in_sizes[0] / 128;
    int ne = in_sizes[1] / 2;
    int np = in_sizes[2] / 2;
    int nn = in_sizes[3] / 2;
    int nb = (n + 1023) / 1024;
    int ne8 = (ne + 7) / 8;
    int tot2 = (np + nn + 1) / 2;

    static bool s_init = false;
    static cudaStream_t s_str1;
    static cudaEvent_t s_ev_fork, s_ev_join, s_ev_pf;
    if (!s_init) {
        cudaStreamCreateWithFlags(&s_str1, cudaStreamNonBlocking);
        cudaEventCreateWithFlags(&s_ev_fork, cudaEventDisableTiming);
        cudaEventCreateWithFlags(&s_ev_join, cudaEventDisableTiming);
        cudaEventCreateWithFlags(&s_ev_pf,   cudaEventDisableTiming);
        s_init = true;
    }

    void* counts_ptr = nullptr;
    cudaGetSymbolAddress(&counts_ptr, g_counts);
    cudaMemsetAsync(counts_ptr, 0, (size_t)n * sizeof(int));

    count_kernel<<<(ne8 + 255) / 256, 256>>>(ei, ne, n);
    reduce_kernel<<<nb, 256>>>(n);                            // writes dis + blocksums

    // Fork: gemm1 (needs only dis) runs concurrently with scan+fill;
    // then prefetch decode indices into L2 during the gather phase.
    cudaEventRecord(s_ev_fork, 0);
    cudaStreamWaitEvent(s_str1, s_ev_fork, 0);
    gemm1_kernel<<<(n + 63) / 64, 128, 0, s_str1>>>(x, W1, n);
    cudaEventRecord(s_ev_join, s_str1);
    prefetch_kernel<<<512, 256, 0, s_str1>>>((const int*)pe, 2 * np,
                                             (const int*)ng, 2 * nn);
    cudaEventRecord(s_ev_pf, s_str1);

    scan_apply_kernel<<<nb, 256>>>(n, nb);                    // inline sums scan
    fill_kernel<<<(ne8 + 255) / 256, 256>>>(ei, ne, n);

    // Join: gather1 needs both g_h (gemm1) and the CSR (fill).
    cudaStreamWaitEvent(0, s_ev_join, 0);
    gather1_gemm2_kernel<<<(n + 7) / 8, 256>>>(b1, W2, n);
    gather2_kernel<<<(n + 7) / 8, 256>>>(b2, n);
    cudaStreamWaitEvent(0, s_ev_pf, 0);                       // join prefetch
    decode_kernel<<<(tot2 + 255) / 256, 256>>>(pe, ng, out, np, nn, n);
}